// round 4
// baseline (speedup 1.0000x reference)
#include <cuda_runtime.h>
#include <cuda_bf16.h>

// Per-row (8 fp32):
//   midv = ascending-sorted row[3]  (== value at descending rank 4)
//   out  = softmax(row) * (row > midv)
// One thread per row (R1 shape). Loads use non-coherent path + L2::256B
// prefetch qualifier to coarsen DRAM requests; stores stay streaming.

#define CSWAP(a, b)                         \
    do {                                    \
        float _lo = fminf((a), (b));        \
        float _hi = fmaxf((a), (b));        \
        (a) = _lo;                          \
        (b) = _hi;                          \
    } while (0)

__device__ __forceinline__ float4 ldg_nc_pf256(const float4* p)
{
    float4 v;
    asm ("ld.global.nc.L2::256B.v4.f32 {%0,%1,%2,%3}, [%4];"
         : "=f"(v.x), "=f"(v.y), "=f"(v.z), "=f"(v.w)
         : "l"(p));
    return v;
}

__global__ void __launch_bounds__(256) hnet3_masked_softmax_kernel(
    const float4* __restrict__ in, float4* __restrict__ out, int nrows)
{
    int r = blockIdx.x * blockDim.x + threadIdx.x;
    if (r >= nrows) return;

    const float4 a = ldg_nc_pf256(&in[2 * r + 0]);
    const float4 b = ldg_nc_pf256(&in[2 * r + 1]);

    float v0 = a.x, v1 = a.y, v2 = a.z, v3 = a.w;
    float v4 = b.x, v5 = b.y, v6 = b.z, v7 = b.w;

    // 19-comparator sorting network; ascending index 3 = midv, index 7 = max.
    float s0 = v0, s1 = v1, s2 = v2, s3 = v3, s4 = v4, s5 = v5, s6 = v6, s7 = v7;
    CSWAP(s0, s1); CSWAP(s2, s3); CSWAP(s4, s5); CSWAP(s6, s7);
    CSWAP(s0, s2); CSWAP(s1, s3); CSWAP(s4, s6); CSWAP(s5, s7);
    CSWAP(s1, s2); CSWAP(s5, s6); CSWAP(s0, s4); CSWAP(s3, s7);
    CSWAP(s1, s5); CSWAP(s2, s6);
    CSWAP(s1, s4); CSWAP(s3, s6);
    CSWAP(s2, s4); CSWAP(s3, s5);
    CSWAP(s3, s4);
    const float midv = s3;
    const float rmax = s7;

    float e0 = __expf(v0 - rmax);
    float e1 = __expf(v1 - rmax);
    float e2 = __expf(v2 - rmax);
    float e3 = __expf(v3 - rmax);
    float e4 = __expf(v4 - rmax);
    float e5 = __expf(v5 - rmax);
    float e6 = __expf(v6 - rmax);
    float e7 = __expf(v7 - rmax);

    float sum = ((e0 + e1) + (e2 + e3)) + ((e4 + e5) + (e6 + e7));
    float inv = 1.0f / sum;

    float4 o0, o1;
    o0.x = (v0 > midv) ? e0 * inv : 0.0f;
    o0.y = (v1 > midv) ? e1 * inv : 0.0f;
    o0.z = (v2 > midv) ? e2 * inv : 0.0f;
    o0.w = (v3 > midv) ? e3 * inv : 0.0f;
    o1.x = (v4 > midv) ? e4 * inv : 0.0f;
    o1.y = (v5 > midv) ? e5 * inv : 0.0f;
    o1.z = (v6 > midv) ? e6 * inv : 0.0f;
    o1.w = (v7 > midv) ? e7 * inv : 0.0f;

    __stcs(&out[2 * r + 0], o0);
    __stcs(&out[2 * r + 1], o1);
}

extern "C" void kernel_launch(void* const* d_in, const int* in_sizes, int n_in,
                              void* d_out, int out_size)
{
    const float4* in = (const float4*)d_in[0];
    float4* out = (float4*)d_out;
    const int nrows = in_sizes[0] / 8;   // 8 fp32 per group

    const int threads = 256;
    const int blocks = (nrows + threads - 1) / threads;
    hnet3_masked_softmax_kernel<<<blocks, threads>>>(in, out, nrows);
}